// round 3
// baseline (speedup 1.0000x reference)
#include <cuda_runtime.h>

// Problem constants
#define Bb 2
#define Hh 16
#define Tt 2048
#define Dd 64
#define Rr 32
#define BHn (Bb*Hh)

#define BM 128
#define BN 32

typedef unsigned long long u64;

// Scratch for low-rank projections (alloc-free rule: __device__ globals)
__device__ float g_qlr[(size_t)BHn * Tt * Rr];
__device__ float g_klr[(size_t)BHn * Tt * Rr];

// ---------- packed f32x2 helpers (sm_103a FFMA2 path) ----------
__device__ __forceinline__ u64 ffma2(u64 a, u64 b, u64 c) {
    u64 d;
    asm("fma.rn.f32x2 %0, %1, %2, %3;" : "=l"(d) : "l"(a), "l"(b), "l"(c));
    return d;
}
__device__ __forceinline__ u64 fmul2(u64 a, u64 b) {
    u64 d;
    asm("mul.rn.f32x2 %0, %1, %2;" : "=l"(d) : "l"(a), "l"(b));
    return d;
}
__device__ __forceinline__ u64 pack2(float x, float y) {
    u64 r;
    asm("mov.b64 %0, {%1, %2};" : "=l"(r) : "f"(x), "f"(y));
    return r;
}
__device__ __forceinline__ float2 unpack2(u64 a) {
    float2 f;
    asm("mov.b64 {%0, %1}, %2;" : "=f"(f.x), "=f"(f.y) : "l"(a));
    return f;
}
__device__ __forceinline__ float ex2(float x) {
    float r;
    asm("ex2.approx.ftz.f32 %0, %1;" : "=f"(r) : "f"(x));
    return r;  // ex2(-inf) -> +0
}

// ---------- Stage 1: low-rank projection ----------
// out[bh, t, r] = sum_d x[bh,t,d] * W[h,d,r]  (* kron[h,r]*scale*log2e for q)
// grid: (BH, T/64), block 256. Each thread owns one r-column of W in regs.
__global__ __launch_bounds__(256) void proj_kernel(
    const float* __restrict__ x, const float* __restrict__ W,
    const float* __restrict__ c1, const float* __restrict__ c2,
    int is_q)
{
    __shared__ float xs[64 * 64];
    const int bh = blockIdx.x;
    const int h  = bh & (Hh - 1);
    const int t0 = blockIdx.y * 64;
    const int tid = threadIdx.x;
    const int r  = tid & 31;
    const int wp = tid >> 5;

    // W column for this thread's r (coalesced across lanes)
    float wreg[64];
    const float* Wp = W + (size_t)h * Dd * Rr + r;
#pragma unroll
    for (int d = 0; d < 64; d++) wreg[d] = Wp[d * Rr];

    // 64 rows of x into smem (4096 floats = 1024 float4)
    {
        const float4* xg = (const float4*)(x + ((size_t)bh * Tt + t0) * Dd);
        float4* xs4 = (float4*)xs;
#pragma unroll
        for (int i = 0; i < 4; i++) xs4[tid + 256 * i] = xg[tid + 256 * i];
    }
    __syncthreads();

    // fold kron * (1/sqrt(R)) * log2(e) into q_lr -> base-2 softmax later
    float mult = 1.0f;
    if (is_q) {
        mult = c1[h * 4 + (r >> 3)] * c2[h * 8 + (r & 7)]
             * (0.17677669529663687f * 1.4426950408889634f);
    }
    float* outp = is_q ? g_qlr : g_klr;

    for (int tt = wp; tt < 64; tt += 8) {
        const float4* xr = (const float4*)(xs + tt * 64);  // warp-uniform -> LDS broadcast
        float acc = 0.0f;
#pragma unroll
        for (int d4 = 0; d4 < 16; d4++) {
            float4 xv = xr[d4];
            acc = fmaf(xv.x, wreg[4 * d4 + 0], acc);
            acc = fmaf(xv.y, wreg[4 * d4 + 1], acc);
            acc = fmaf(xv.z, wreg[4 * d4 + 2], acc);
            acc = fmaf(xv.w, wreg[4 * d4 + 3], acc);
        }
        outp[((size_t)bh * Tt + t0 + tt) * Rr + r] = acc * mult;
    }
}

// ---------- Stage 2: causal flash attention over rank-32 scores ----------
// One query row per thread. Block = 128 threads = 128 rows.
// grid: (T/BM = 16, BH = 32); heavy m-tiles launch first.
__global__ __launch_bounds__(128) void flash_kernel(
    const float* __restrict__ v, float* __restrict__ out)
{
    __shared__ float4 ks4[BN * 8];   // 32 keys x 32 floats
    __shared__ float4 vs4[BN * 16];  // 32 keys x 64 floats

    const int bh  = blockIdx.y;
    const int mt  = (int)gridDim.x - 1 - (int)blockIdx.x;  // heavy first
    const int m0  = mt * BM;
    const int tid = threadIdx.x;
    const int row = m0 + tid;

    // q_lr row -> 16 packed f32x2 regs
    u64 q2[16];
    {
        const ulonglong2* qp =
            (const ulonglong2*)(g_qlr + ((size_t)bh * Tt + row) * Rr);
#pragma unroll
        for (int i = 0; i < 8; i++) {
            ulonglong2 t = qp[i];
            q2[2 * i] = t.x; q2[2 * i + 1] = t.y;
        }
    }

    u64 o2[32];
#pragma unroll
    for (int i = 0; i < 32; i++) o2[i] = 0ull;

    const float NEG_INF = __int_as_float(0xff800000);
    float mrun = NEG_INF;
    float l = 0.0f;

    const int nfull = m0 / BN;             // fully-unmasked key tiles
    const int ntiles = nfull + (BM / BN);  // + 4 diagonal tiles

    for (int nt = 0; nt < ntiles; nt++) {
        const int n0 = nt * BN;

        // cooperative tile load (contiguous in memory)
        {
            const float4* kg = (const float4*)(g_klr + ((size_t)bh * Tt + n0) * Rr);
            const float4* vg = (const float4*)(v + ((size_t)bh * Tt + n0) * Dd);
            ks4[tid]       = kg[tid];
            ks4[tid + 128] = kg[tid + 128];
#pragma unroll
            for (int i = 0; i < 4; i++) vs4[tid + 128 * i] = vg[tid + 128 * i];
        }
        __syncthreads();

        const bool masked = (nt >= nfull);
        if (!masked || row >= n0) {
            // scores (packed dot over R=32)
            float s[BN];
#pragma unroll
            for (int j = 0; j < BN; j++) {
                const ulonglong2* kr = (const ulonglong2*)(ks4 + j * 8);
                u64 acc = 0ull;
#pragma unroll
                for (int i = 0; i < 8; i++) {
                    ulonglong2 t = kr[i];  // warp-uniform broadcast LDS.128
                    acc = ffma2(q2[2 * i],     t.x, acc);
                    acc = ffma2(q2[2 * i + 1], t.y, acc);
                }
                float2 a = unpack2(acc);
                s[j] = a.x + a.y;
            }
            if (masked) {
#pragma unroll
                for (int j = 0; j < BN; j++)
                    if (n0 + j > row) s[j] = NEG_INF;
            }

            // online softmax (base-2; log2e folded into q_lr)
            float tmax = s[0];
#pragma unroll
            for (int j = 1; j < BN; j++) tmax = fmaxf(tmax, s[j]);
            const float mnew  = fmaxf(mrun, tmax);
            const float alpha = ex2(mrun - mnew);  // first tile: ex2(-inf)=0
            l *= alpha;
            const u64 alpha2 = pack2(alpha, alpha);
#pragma unroll
            for (int i = 0; i < 32; i++) o2[i] = fmul2(o2[i], alpha2);
            mrun = mnew;

            // P·V accumulation (packed)
#pragma unroll
            for (int j = 0; j < BN; j++) {
                const float p = ex2(s[j] - mnew);
                l += p;
                const u64 p2 = pack2(p, p);
                const ulonglong2* vr = (const ulonglong2*)(vs4 + j * 16);
#pragma unroll
                for (int i = 0; i < 16; i++) {
                    ulonglong2 t = vr[i];  // warp-uniform broadcast
                    o2[2 * i]     = ffma2(p2, t.x, o2[2 * i]);
                    o2[2 * i + 1] = ffma2(p2, t.y, o2[2 * i + 1]);
                }
            }
        }
        __syncthreads();
    }

    // normalize + store
    const float inv = 1.0f / l;
    const u64 inv2 = pack2(inv, inv);
    float4* og = (float4*)(out + ((size_t)bh * Tt + row) * Dd);
#pragma unroll
    for (int i = 0; i < 16; i++) {
        float2 a = unpack2(fmul2(o2[2 * i],     inv2));
        float2 b = unpack2(fmul2(o2[2 * i + 1], inv2));
        og[i] = make_float4(a.x, a.y, b.x, b.y);
    }
}

// ---------- launch ----------
extern "C" void kernel_launch(void* const* d_in, const int* in_sizes, int n_in,
                              void* d_out, int out_size)
{
    const float* q  = (const float*)d_in[0];
    const float* k  = (const float*)d_in[1];
    const float* v  = (const float*)d_in[2];
    const float* Wq = (const float*)d_in[3];
    const float* Wk = (const float*)d_in[4];
    const float* c1 = (const float*)d_in[5];
    const float* c2 = (const float*)d_in[6];
    float* out = (float*)d_out;

    dim3 pg(BHn, Tt / 64);
    proj_kernel<<<pg, 256>>>(q, Wq, c1, c2, 1);
    proj_kernel<<<pg, 256>>>(k, Wk, c1, c2, 0);

    dim3 fg(Tt / BM, BHn);
    flash_kernel<<<fg, 128>>>(v, out);
}